// round 12
// baseline (speedup 1.0000x reference)
#include <cuda_runtime.h>
#include <cuda_bf16.h>
#include <stdint.h>

#define B_     2
#define N_     65536
#define M_     16384
#define K_     32
#define KP_    15
#define DIN_   64
#define DOUT_  128
#define KTOT   960           // KP_*DIN_
#define SHADOW (-1000.0f)

// ---------------------------------------------------------------------------
// Scratch (__device__ globals per no-allocation rule)
// ---------------------------------------------------------------------------
__device__ float g_featT[(size_t)B_ * N_ * DIN_];                       // 33.5 MB
__device__ __align__(16) __nv_bfloat16 g_whi[(size_t)B_ * M_ * KTOT];   // 60 MB
__device__ __align__(16) __nv_bfloat16 g_wlo[(size_t)B_ * M_ * KTOT];   // 60 MB
__device__ __align__(16) __nv_bfloat16 g_bhi[DOUT_ * KTOT];             // W^T hi
__device__ __align__(16) __nv_bfloat16 g_blo[DOUT_ * KTOT];             // W^T lo

// ---------------------------------------------------------------------------
// helpers
// ---------------------------------------------------------------------------
__device__ __forceinline__ uint32_t smem_u32(const void* p) {
    uint32_t a;
    asm("{ .reg .u64 t; cvta.to.shared.u64 t, %1; cvt.u32.u64 %0, t; }"
        : "=r"(a) : "l"(p));
    return a;
}
__device__ __forceinline__ void ldsm4(uint32_t& r0, uint32_t& r1,
                                      uint32_t& r2, uint32_t& r3, uint32_t addr) {
    asm volatile("ldmatrix.sync.aligned.m8n8.x4.shared.b16 {%0,%1,%2,%3}, [%4];"
                 : "=r"(r0), "=r"(r1), "=r"(r2), "=r"(r3) : "r"(addr));
}
__device__ __forceinline__ void ldsm4t(uint32_t& r0, uint32_t& r1,
                                       uint32_t& r2, uint32_t& r3, uint32_t addr) {
    asm volatile("ldmatrix.sync.aligned.m8n8.x4.trans.shared.b16 {%0,%1,%2,%3}, [%4];"
                 : "=r"(r0), "=r"(r1), "=r"(r2), "=r"(r3) : "r"(addr));
}
__device__ __forceinline__ void mma16816(float* c, const uint32_t* a,
                                         const uint32_t* b) {
    asm volatile("mma.sync.aligned.m16n8k16.row.col.f32.bf16.bf16.f32 "
                 "{%0,%1,%2,%3}, {%4,%5,%6,%7}, {%8,%9}, {%0,%1,%2,%3};"
                 : "+f"(c[0]), "+f"(c[1]), "+f"(c[2]), "+f"(c[3])
                 : "r"(a[0]), "r"(a[1]), "r"(a[2]), "r"(a[3]),
                   "r"(b[0]), "r"(b[1]));
}
__device__ __forceinline__ void cpasync16(uint32_t dst, const void* src) {
    asm volatile("cp.async.ca.shared.global [%0], [%1], 16;" :: "r"(dst), "l"(src));
}
__device__ __forceinline__ void cp_commit() {
    asm volatile("cp.async.commit_group;" ::: "memory");
}
__device__ __forceinline__ void cp_wait1() {
    asm volatile("cp.async.wait_group 1;" ::: "memory");
}
__device__ __forceinline__ void cp_wait0() {
    asm volatile("cp.async.wait_group 0;" ::: "memory");
}
// pack two floats -> bf16x2 word (a in low half)
__device__ __forceinline__ uint32_t pkbf2(float a, float b) {
    __nv_bfloat162 t = __floats2bfloat162_rn(a, b);
    return *(uint32_t*)&t;
}

// ---------------------------------------------------------------------------
// Kernel 1: transpose features [B][Din][N] -> g_featT [B][N][Din]
// ---------------------------------------------------------------------------
__global__ void transpose_feat_kernel(const float* __restrict__ f)
{
    __shared__ float tile[32][33];
    const int b  = blockIdx.z;
    const int n0 = blockIdx.x * 32;
    const int d0 = blockIdx.y * 32;
    const int x = threadIdx.x, y = threadIdx.y;

    #pragma unroll
    for (int i = y; i < 32; i += 8)
        tile[i][x] = f[((size_t)b * DIN_ + (d0 + i)) * N_ + n0 + x];
    __syncthreads();
    #pragma unroll
    for (int i = y; i < 32; i += 8)
        g_featT[((size_t)b * N_ + (n0 + i)) * DIN_ + d0 + x] = tile[x][i];
}

// ---------------------------------------------------------------------------
// Kernel 1b: weights [Kp][Din][Dout] -> g_bhi/g_blo [Dout rows][KTOT cols]
// ---------------------------------------------------------------------------
__global__ void prep_w_kernel(const float* __restrict__ w)
{
    const int e = blockIdx.x * 256 + threadIdx.x;
    if (e >= KP_ * DIN_ * DOUT_) return;
    const int kp = e / DOUT_, o = e % DOUT_;
    const float v = w[e];
    const __nv_bfloat16 hi = __float2bfloat16(v);
    const __nv_bfloat16 lo = __float2bfloat16(v - __bfloat162float(hi));
    g_bhi[o * KTOT + kp] = hi;
    g_blo[o * KTOT + kp] = lo;
}

// ---------------------------------------------------------------------------
// Kernel 2: einsum1 on tensor cores. warp <-> point; 4 points per 128-thr CTA.
//   v4: 28KB/CTA -> 8 CTAs/SM = 64 resident warps.
// NOTE: neighbor_indices is int32 (JAX canonicalizes int64 -> int32).
// ---------------------------------------------------------------------------
#define PTS2   4
#define FSTR   72                        // feat smem row stride (elems)
#define WSTR   40                        // w smem row stride (elems)
#define F_BYTES (16 * FSTR * 2)          // 2304 (16-row chunk buffer)
#define W_BYTES (16 * WSTR * 2)          // 1280
#define PT_BYTES (2 * F_BYTES + 2 * W_BYTES)   // 7168
#define K2_SMEM (PTS2 * PT_BYTES)        // 28672

__global__ __launch_bounds__(128)
void kpconv_weighted_mma(const float* __restrict__ points_xyz,
                         const float* __restrict__ center_xyz,
                         const int* __restrict__ nidx,
                         const float* __restrict__ kernel_points)
{
    extern __shared__ __align__(16) char k2sm[];
    const int wpt  = threadIdx.x >> 5;   // warp id == local point id
    const int lane = threadIdx.x & 31;
    const int bm   = blockIdx.x * PTS2 + wpt;
    const int b    = bm >> 14;

    __nv_bfloat16* sFh = (__nv_bfloat16*)(k2sm + wpt * PT_BYTES);
    __nv_bfloat16* sFl = sFh + 16 * FSTR;
    __nv_bfloat16* sWh = sFl + 16 * FSTR;
    __nv_bfloat16* sWl = sWh + 16 * WSTR;

    // ---- phase 1: lane = k; coords in registers
    const int ii0 = nidx[(size_t)bm * K_ + lane];
    const bool valid = (unsigned)ii0 < (unsigned)N_;
    const int idx = valid ? ii0 : 0;
    float px = SHADOW, py = SHADOW, pz = SHADOW;
    if (valid) {
        const float* pp = points_xyz + ((size_t)b * N_ + ii0) * 3;
        px = pp[0]; py = pp[1]; pz = pp[2];
    }
    const float rx = px - center_xyz[bm * 3 + 0];
    const float ry = py - center_xyz[bm * 3 + 1];
    const float rz = pz - center_xyz[bm * 3 + 2];
    float md = sqrtf(rx * rx + ry * ry + rz * rz);
    #pragma unroll
    for (int o = 16; o; o >>= 1)
        md = fmaxf(md, __shfl_xor_sync(0xffffffffu, md, o));
    const float inv = 1.0f / (md / 2.1f + 1e-5f);

    // ---- phase 2: w[p] -> A smem [p][k=lane], bf16 hi/lo; row 15 zero
    #pragma unroll
    for (int p = 0; p < KP_; ++p) {
        const float kx = kernel_points[p * 3 + 0] * md;
        const float ky = kernel_points[p * 3 + 1] * md;
        const float kz = kernel_points[p * 3 + 2] * md;
        const float dx = rx - kx, dy = ry - ky, dz = rz - kz;
        float w = 1.0f - sqrtf(dx * dx + dy * dy + dz * dz) * inv;
        w = valid ? fmaxf(w, 0.0f) : 0.0f;
        const __nv_bfloat16 h = __float2bfloat16(w);
        sWh[p * WSTR + lane] = h;
        sWl[p * WSTR + lane] = __float2bfloat16(w - __bfloat162float(h));
    }
    sWh[15 * WSTR + lane] = __float2bfloat16(0.0f);
    sWl[15 * WSTR + lane] = __float2bfloat16(0.0f);

    float acc[8][4];
    #pragma unroll
    for (int j = 0; j < 8; ++j)
        #pragma unroll
        for (int q = 0; q < 4; ++q) acc[j][q] = 0.0f;

    const int ltile = lane >> 3, lr = lane & 7;
    const int aRow = (ltile & 1) * 8 + lr;
    const int aCol = (ltile >> 1) * 8;
    const int bRow = (ltile & 1) * 8 + lr;
    const int bCol = (ltile >> 1) * 8;
    const int rlane = lane & 15;          // float4 slot within feat row
    const int rhalf = lane >> 4;          // which of 2 rows per pass
    const float4* gfb = (const float4*)(g_featT + (size_t)b * N_ * DIN_);

    #pragma unroll
    for (int kc = 0; kc < 2; ++kc) {
        // ---- gather 16 feat rows of this K-chunk (coalesced, MLP=8/lane)
        #pragma unroll
        for (int it = 0; it < 8; ++it) {
            const int kl = 2 * it + rhalf;           // local row 0..15
            const int ik = __shfl_sync(0xffffffffu, idx, kc * 16 + kl);
            const float4 f = gfb[(size_t)ik * 16 + rlane];
            const uint32_t h0 = pkbf2(f.x, f.y);
            const uint32_t h1 = pkbf2(f.z, f.w);
            const __nv_bfloat162 hh0 = *(const __nv_bfloat162*)&h0;
            const __nv_bfloat162 hh1 = *(const __nv_bfloat162*)&h1;
            const uint32_t l0 = pkbf2(f.x - __bfloat162float(hh0.x),
                                      f.y - __bfloat162float(hh0.y));
            const uint32_t l1 = pkbf2(f.z - __bfloat162float(hh1.x),
                                      f.w - __bfloat162float(hh1.y));
            *(uint2*)&sFh[kl * FSTR + rlane * 4] = make_uint2(h0, h1);
            *(uint2*)&sFl[kl * FSTR + rlane * 4] = make_uint2(l0, l1);
        }
        __syncwarp();

        // ---- A frags for this k-chunk + B frags, 24 mma
        uint32_t ah[4], al[4];
        const uint32_t aOff = (uint32_t)(aRow * WSTR + kc * 16 + aCol) * 2;
        ldsm4(ah[0], ah[1], ah[2], ah[3], smem_u32(sWh) + aOff);
        ldsm4(al[0], al[1], al[2], al[3], smem_u32(sWl) + aOff);
        #pragma unroll
        for (int g = 0; g < 4; ++g) {                // n in 16-wide groups
            const uint32_t bOff = (uint32_t)(bRow * FSTR + g * 16 + bCol) * 2;
            uint32_t bh[4], bl[4];
            ldsm4t(bh[0], bh[1], bh[2], bh[3], smem_u32(sFh) + bOff);
            ldsm4t(bl[0], bl[1], bl[2], bl[3], smem_u32(sFl) + bOff);
            #pragma unroll
            for (int half = 0; half < 2; ++half) {
                const int nt = 2 * g + half;
                mma16816(acc[nt], ah, bh + 2 * half);
                mma16816(acc[nt], al, bh + 2 * half);
                mma16816(acc[nt], ah, bl + 2 * half);
            }
        }
        __syncwarp();          // frags in regs; safe to overwrite buffer
    }

    // ---- epilogue: stage [p][64] into reused sFh/sFl, then coalesced
    // uint4 copy of the 960-elem row (120 uint4) to gmem.
    const int r  = lane >> 2;
    const int cb = 2 * (lane & 3);
    #pragma unroll
    for (int nt = 0; nt < 8; ++nt) {
        const int d0 = nt * 8 + cb;
        {   // p = r (0..7)
            const uint32_t h01 = pkbf2(acc[nt][0], acc[nt][1]);
            const __nv_bfloat162 hp = *(const __nv_bfloat162*)&h01;
            const uint32_t l01 = pkbf2(acc[nt][0] - __bfloat162float(hp.x),
                                       acc[nt][1] - __bfloat162float(hp.y));
            *(uint32_t*)&sFh[r * 64 + d0] = h01;
            *(uint32_t*)&sFl[r * 64 + d0] = l01;
        }
        {   // p = r+8 (8..15; row 15 staged but never copied out)
            const uint32_t h23 = pkbf2(acc[nt][2], acc[nt][3]);
            const __nv_bfloat162 hp = *(const __nv_bfloat162*)&h23;
            const uint32_t l23 = pkbf2(acc[nt][2] - __bfloat162float(hp.x),
                                       acc[nt][3] - __bfloat162float(hp.y));
            *(uint32_t*)&sFh[(r + 8) * 64 + d0] = h23;
            *(uint32_t*)&sFl[(r + 8) * 64 + d0] = l23;
        }
    }
    __syncwarp();

    {
        const uint4* eh = (const uint4*)sFh;
        const uint4* el = (const uint4*)sFl;
        uint4* wh = (uint4*)(g_whi + (size_t)bm * KTOT);
        uint4* wl = (uint4*)(g_wlo + (size_t)bm * KTOT);
        #pragma unroll
        for (int i = 0; i < 4; ++i) {
            const int e = lane + i * 32;      // 0..127, need 0..119
            if (e < 120) { wh[e] = eh[e]; wl[e] = el[e]; }
        }
    }
}

// ---------------------------------------------------------------------------
// Kernel 3: mma.sync bf16 GEMM, 3-term hi/lo split, cp.async double buffer.
//   v2: 512 threads (16 warps), warp tile 32x32 — 2x warps to hide
//   ldsm/mma latency through the per-chunk sync points.
// ---------------------------------------------------------------------------
#define BK    32
#define LDS_  40                 // row stride (elements): 80B, ldsm conflict-free
#define ARR_BYTES  (128 * LDS_ * 2)          // 10240 B per array
#define STAGE_BYTES (4 * ARR_BYTES)          // Ah, Al, Bh, Bl
#define GEMM_SMEM  (2 * STAGE_BYTES)         // 81920 B

__global__ __launch_bounds__(512)
void kpconv_mma_gemm(float* __restrict__ out)
{
    extern __shared__ __align__(16) char sm[];
    const uint32_t smem_base = smem_u32(sm);

    const int tid  = threadIdx.x;
    const int wid  = tid >> 5, lane = tid & 31;
    const int wm   = wid & 3;        // warp m-offset: wm*32
    const int wn   = wid >> 2;       // warp n-offset: wn*32 (0..3)
    const size_t rowBase = (size_t)blockIdx.x * 128;

    auto issue_chunk = [&](int c, int stage) {
        const uint32_t sb = smem_base + stage * STAGE_BYTES;
        #pragma unroll
        for (int i = 0; i < 4; ++i) {
            const int idx = tid + i * 512;
            const int arr = idx >> 9;           // 0..3
            const int rem = idx & 511;
            const int row = rem >> 2, seg = rem & 3;
            const uint32_t dst = sb + arr * ARR_BYTES + (row * LDS_ + seg * 8) * 2;
            const __nv_bfloat16* src;
            if (arr == 0)      src = g_whi + (rowBase + row) * KTOT + c * BK + seg * 8;
            else if (arr == 1) src = g_wlo + (rowBase + row) * KTOT + c * BK + seg * 8;
            else if (arr == 2) src = g_bhi + (size_t)row * KTOT + c * BK + seg * 8;
            else               src = g_blo + (size_t)row * KTOT + c * BK + seg * 8;
            cpasync16(dst, src);
        }
        cp_commit();
    };

    float acc[2][4][4];
    #pragma unroll
    for (int i = 0; i < 2; i++)
        #pragma unroll
        for (int j = 0; j < 4; j++)
            #pragma unroll
            for (int q = 0; q < 4; q++) acc[i][j][q] = 0.0f;

    // per-lane ldmatrix row/col patterns
    const int ltile = lane >> 3, lr = lane & 7;
    const int aRow = (ltile & 1) * 8 + lr;
    const int aCol = (ltile >> 1) * 8;
    const int bRow = (ltile >> 1) * 8 + lr;
    const int bCol = (ltile & 1) * 8;

    issue_chunk(0, 0);

    for (int c = 0; c < KTOT / BK; ++c) {
        if (c + 1 < KTOT / BK) { issue_chunk(c + 1, (c + 1) & 1); cp_wait1(); }
        else                   { cp_wait0(); }
        __syncthreads();

        const uint32_t sb  = smem_base + (c & 1) * STAGE_BYTES;
        const uint32_t pAh = sb;
        const uint32_t pAl = sb + ARR_BYTES;
        const uint32_t pBh = sb + 2 * ARR_BYTES;
        const uint32_t pBl = sb + 3 * ARR_BYTES;

        #pragma unroll
        for (int kk = 0; kk < 2; ++kk) {
            const int kcol = kk * 16;
            uint32_t afh[2][4], afl[2][4];
            #pragma unroll
            for (int mt = 0; mt < 2; ++mt) {
                const int row = wm * 32 + mt * 16 + aRow;
                const int col = kcol + aCol;
                const uint32_t off = (uint32_t)(row * LDS_ + col) * 2;
                ldsm4(afh[mt][0], afh[mt][1], afh[mt][2], afh[mt][3], pAh + off);
                ldsm4(afl[mt][0], afl[mt][1], afl[mt][2], afl[mt][3], pAl + off);
            }
            #pragma unroll
            for (int g = 0; g < 2; ++g) {           // n in 16-wide groups
                const int row = wn * 32 + g * 16 + bRow;
                const int col = kcol + bCol;
                const uint32_t off = (uint32_t)(row * LDS_ + col) * 2;
                uint32_t bh[4], bl[4];
                ldsm4(bh[0], bh[1], bh[2], bh[3], pBh + off);
                ldsm4(bl[0], bl[1], bl[2], bl[3], pBl + off);
                #pragma unroll
                for (int half = 0; half < 2; ++half) {
                    const int nt = 2 * g + half;
                    #pragma unroll
                    for (int mt = 0; mt < 2; ++mt) {
                        mma16816(acc[mt][nt], afh[mt], bh + 2 * half);
                        mma16816(acc[mt][nt], afl[mt], bh + 2 * half);
                        mma16816(acc[mt][nt], afh[mt], bl + 2 * half);
                    }
                }
            }
        }
        __syncthreads();
    }

    // epilogue: c0:(r,c) c1:(r,c+1) c2:(r+8,c) c3:(r+8,c+1)
    const int bb     = (int)(rowBase >> 14);
    const int mLocal = (int)(rowBase & 16383);
    #pragma unroll
    for (int mt = 0; mt < 2; ++mt)
        #pragma unroll
        for (int nt = 0; nt < 4; ++nt) {
            const int m0 = mLocal + wm * 32 + mt * 16 + (lane >> 2);
            const int n0 = wn * 32 + nt * 8 + 2 * (lane & 3);
            float* o0 = out + ((size_t)bb * DOUT_ + n0) * M_ + m0;
            o0[0]      = acc[mt][nt][0];
            o0[M_]     = acc[mt][nt][1];
            o0[8]      = acc[mt][nt][2];
            o0[M_ + 8] = acc[mt][nt][3];
        }
}

// ---------------------------------------------------------------------------
extern "C" void kernel_launch(void* const* d_in, const int* in_sizes, int n_in,
                              void* d_out, int out_size)
{
    // Dispatch inputs by (pairwise-distinct) element count:
    const float* points_xyz    = nullptr;
    const float* features      = nullptr;
    const float* center_xyz    = nullptr;
    const int*   neighbor_idx  = nullptr;
    const float* kernel_points = nullptr;
    const float* weights       = nullptr;

    for (int i = 0; i < n_in; i++) {
        switch (in_sizes[i]) {
            case 393216:  points_xyz    = (const float*)d_in[i]; break;
            case 8388608: features      = (const float*)d_in[i]; break;
            case 98304:   center_xyz    = (const float*)d_in[i]; break;
            case 1048576: neighbor_idx  = (const int*)d_in[i];   break;
            case 45:      kernel_points = (const float*)d_in[i]; break;
            case 122880:  weights       = (const float*)d_in[i]; break;
            default: break;
        }
    }
    float* out = (float*)d_out;

    cudaFuncSetAttribute(kpconv_mma_gemm,
                         cudaFuncAttributeMaxDynamicSharedMemorySize, GEMM_SMEM);
    cudaFuncSetAttribute(kpconv_weighted_mma,
                         cudaFuncAttributeMaxDynamicSharedMemorySize, K2_SMEM);
    cudaFuncSetAttribute(kpconv_weighted_mma,
                         cudaFuncAttributePreferredSharedMemoryCarveout, 100);

    dim3 g1(N_ / 32, DIN_ / 32, B_);
    transpose_feat_kernel<<<g1, dim3(32, 8)>>>(features);

    prep_w_kernel<<<(KP_ * DIN_ * DOUT_ + 255) / 256, 256>>>(weights);

    kpconv_weighted_mma<<<(B_ * M_) / PTS2, 128, K2_SMEM>>>(
        points_xyz, center_xyz, neighbor_idx, kernel_points);

    kpconv_mma_gemm<<<(B_ * M_) / 128, 512, GEMM_SMEM>>>(out);
}

// round 13
// speedup vs baseline: 1.2108x; 1.2108x over previous
#include <cuda_runtime.h>
#include <cuda_bf16.h>
#include <cuda_fp16.h>
#include <stdint.h>

#define B_     2
#define N_     65536
#define M_     16384
#define K_     32
#define KP_    15
#define DIN_   64
#define DOUT_  128
#define KTOT   960           // KP_*DIN_
#define SHADOW (-1000.0f)

// ---------------------------------------------------------------------------
// Scratch (__device__ globals per no-allocation rule)
// ---------------------------------------------------------------------------
__device__ float g_featT[(size_t)B_ * N_ * DIN_];                  // 33.5 MB
__device__ __align__(16) __half g_ahi[(size_t)B_ * M_ * KTOT];     // 60 MB (A hi)
__device__ __align__(16) __half g_alo[(size_t)B_ * M_ * KTOT];     // 60 MB (A lo)
__device__ __align__(16) __half g_bh[DOUT_ * KTOT];                // W^T fp16

// ---------------------------------------------------------------------------
// helpers
// ---------------------------------------------------------------------------
__device__ __forceinline__ uint32_t smem_u32(const void* p) {
    uint32_t a;
    asm("{ .reg .u64 t; cvta.to.shared.u64 t, %1; cvt.u32.u64 %0, t; }"
        : "=r"(a) : "l"(p));
    return a;
}
__device__ __forceinline__ void ldsm4(uint32_t& r0, uint32_t& r1,
                                      uint32_t& r2, uint32_t& r3, uint32_t addr) {
    asm volatile("ldmatrix.sync.aligned.m8n8.x4.shared.b16 {%0,%1,%2,%3}, [%4];"
                 : "=r"(r0), "=r"(r1), "=r"(r2), "=r"(r3) : "r"(addr));
}
__device__ __forceinline__ void ldsm4t(uint32_t& r0, uint32_t& r1,
                                       uint32_t& r2, uint32_t& r3, uint32_t addr) {
    asm volatile("ldmatrix.sync.aligned.m8n8.x4.trans.shared.b16 {%0,%1,%2,%3}, [%4];"
                 : "=r"(r0), "=r"(r1), "=r"(r2), "=r"(r3) : "r"(addr));
}
// bf16 mma (kernel2 internal 3-term path)
__device__ __forceinline__ void mma_bf16(float* c, const uint32_t* a,
                                         const uint32_t* b) {
    asm volatile("mma.sync.aligned.m16n8k16.row.col.f32.bf16.bf16.f32 "
                 "{%0,%1,%2,%3}, {%4,%5,%6,%7}, {%8,%9}, {%0,%1,%2,%3};"
                 : "+f"(c[0]), "+f"(c[1]), "+f"(c[2]), "+f"(c[3])
                 : "r"(a[0]), "r"(a[1]), "r"(a[2]), "r"(a[3]),
                   "r"(b[0]), "r"(b[1]));
}
// fp16 mma (big GEMM 2-term path)
__device__ __forceinline__ void mma_f16(float* c, const uint32_t* a,
                                        const uint32_t* b) {
    asm volatile("mma.sync.aligned.m16n8k16.row.col.f32.f16.f16.f32 "
                 "{%0,%1,%2,%3}, {%4,%5,%6,%7}, {%8,%9}, {%0,%1,%2,%3};"
                 : "+f"(c[0]), "+f"(c[1]), "+f"(c[2]), "+f"(c[3])
                 : "r"(a[0]), "r"(a[1]), "r"(a[2]), "r"(a[3]),
                   "r"(b[0]), "r"(b[1]));
}
__device__ __forceinline__ void cpasync16(uint32_t dst, const void* src) {
    asm volatile("cp.async.ca.shared.global [%0], [%1], 16;" :: "r"(dst), "l"(src));
}
__device__ __forceinline__ void cp_commit() {
    asm volatile("cp.async.commit_group;" ::: "memory");
}
__device__ __forceinline__ void cp_wait1() {
    asm volatile("cp.async.wait_group 1;" ::: "memory");
}
__device__ __forceinline__ void cp_wait0() {
    asm volatile("cp.async.wait_group 0;" ::: "memory");
}
// pack two floats -> bf16x2 / f16x2 words
__device__ __forceinline__ uint32_t pkbf2(float a, float b) {
    __nv_bfloat162 t = __floats2bfloat162_rn(a, b);
    return *(uint32_t*)&t;
}
__device__ __forceinline__ uint32_t pkhf2(float a, float b) {
    __half2 t = __floats2half2_rn(a, b);
    return *(uint32_t*)&t;
}

// ---------------------------------------------------------------------------
// Kernel 1: transpose features [B][Din][N] -> g_featT [B][N][Din]
// ---------------------------------------------------------------------------
__global__ void transpose_feat_kernel(const float* __restrict__ f)
{
    __shared__ float tile[32][33];
    const int b  = blockIdx.z;
    const int n0 = blockIdx.x * 32;
    const int d0 = blockIdx.y * 32;
    const int x = threadIdx.x, y = threadIdx.y;

    #pragma unroll
    for (int i = y; i < 32; i += 8)
        tile[i][x] = f[((size_t)b * DIN_ + (d0 + i)) * N_ + n0 + x];
    __syncthreads();
    #pragma unroll
    for (int i = y; i < 32; i += 8)
        g_featT[((size_t)b * N_ + (n0 + i)) * DIN_ + d0 + x] = tile[x][i];
}

// ---------------------------------------------------------------------------
// Kernel 1b: weights [Kp][Din][Dout] -> g_bh [Dout rows][KTOT cols] (fp16)
// ---------------------------------------------------------------------------
__global__ void prep_w_kernel(const float* __restrict__ w)
{
    const int e = blockIdx.x * 256 + threadIdx.x;
    if (e >= KP_ * DIN_ * DOUT_) return;
    const int kp = e / DOUT_, o = e % DOUT_;
    g_bh[o * KTOT + kp] = __float2half_rn(w[e]);
}

// ---------------------------------------------------------------------------
// Kernel 2: einsum1 on tensor cores (R11 config: 8 points/256-thr CTA,
//   16-row chunked F buffer, bf16 3-term internal math).
//   Epilogue emits fp16 hi/lo A operand for the big GEMM.
// NOTE: neighbor_indices is int32 (JAX canonicalizes int64 -> int32).
// ---------------------------------------------------------------------------
#define PTS2   8
#define FSTR   72                        // feat smem row stride (elems)
#define WSTR   40                        // w smem row stride (elems)
#define F_BYTES (16 * FSTR * 2)          // 2304 (16-row chunk buffer)
#define W_BYTES (16 * WSTR * 2)          // 1280
#define PT_BYTES (2 * F_BYTES + 2 * W_BYTES)   // 7168
#define K2_SMEM (PTS2 * PT_BYTES)        // 57344

__global__ __launch_bounds__(256)
void kpconv_weighted_mma(const float* __restrict__ points_xyz,
                         const float* __restrict__ center_xyz,
                         const int* __restrict__ nidx,
                         const float* __restrict__ kernel_points)
{
    extern __shared__ __align__(16) char k2sm[];
    const int wpt  = threadIdx.x >> 5;   // warp id == local point id
    const int lane = threadIdx.x & 31;
    const int bm   = blockIdx.x * PTS2 + wpt;
    const int b    = bm >> 14;

    __nv_bfloat16* sFh = (__nv_bfloat16*)(k2sm + wpt * PT_BYTES);
    __nv_bfloat16* sFl = sFh + 16 * FSTR;
    __nv_bfloat16* sWh = sFl + 16 * FSTR;
    __nv_bfloat16* sWl = sWh + 16 * WSTR;

    // ---- phase 1: lane = k; coords in registers
    const int ii0 = nidx[(size_t)bm * K_ + lane];
    const bool valid = (unsigned)ii0 < (unsigned)N_;
    const int idx = valid ? ii0 : 0;
    float px = SHADOW, py = SHADOW, pz = SHADOW;
    if (valid) {
        const float* pp = points_xyz + ((size_t)b * N_ + ii0) * 3;
        px = pp[0]; py = pp[1]; pz = pp[2];
    }
    const float rx = px - center_xyz[bm * 3 + 0];
    const float ry = py - center_xyz[bm * 3 + 1];
    const float rz = pz - center_xyz[bm * 3 + 2];
    float md = sqrtf(rx * rx + ry * ry + rz * rz);
    #pragma unroll
    for (int o = 16; o; o >>= 1)
        md = fmaxf(md, __shfl_xor_sync(0xffffffffu, md, o));
    const float inv = 1.0f / (md / 2.1f + 1e-5f);

    // ---- phase 2: w[p] -> A smem [p][k=lane], bf16 hi/lo; row 15 zero
    #pragma unroll
    for (int p = 0; p < KP_; ++p) {
        const float kx = kernel_points[p * 3 + 0] * md;
        const float ky = kernel_points[p * 3 + 1] * md;
        const float kz = kernel_points[p * 3 + 2] * md;
        const float dx = rx - kx, dy = ry - ky, dz = rz - kz;
        float w = 1.0f - sqrtf(dx * dx + dy * dy + dz * dz) * inv;
        w = valid ? fmaxf(w, 0.0f) : 0.0f;
        const __nv_bfloat16 h = __float2bfloat16(w);
        sWh[p * WSTR + lane] = h;
        sWl[p * WSTR + lane] = __float2bfloat16(w - __bfloat162float(h));
    }
    sWh[15 * WSTR + lane] = __float2bfloat16(0.0f);
    sWl[15 * WSTR + lane] = __float2bfloat16(0.0f);

    float acc[8][4];
    #pragma unroll
    for (int j = 0; j < 8; ++j)
        #pragma unroll
        for (int q = 0; q < 4; ++q) acc[j][q] = 0.0f;

    const int ltile = lane >> 3, lr = lane & 7;
    const int aRow = (ltile & 1) * 8 + lr;
    const int aCol = (ltile >> 1) * 8;
    const int bRow = (ltile & 1) * 8 + lr;
    const int bCol = (ltile >> 1) * 8;
    const int rlane = lane & 15;          // float4 slot within feat row
    const int rhalf = lane >> 4;          // which of 2 rows per pass
    const float4* gfb = (const float4*)(g_featT + (size_t)b * N_ * DIN_);

    #pragma unroll
    for (int kc = 0; kc < 2; ++kc) {
        // ---- gather 16 feat rows of this K-chunk (coalesced, MLP=8/lane)
        #pragma unroll
        for (int it = 0; it < 8; ++it) {
            const int kl = 2 * it + rhalf;           // local row 0..15
            const int ik = __shfl_sync(0xffffffffu, idx, kc * 16 + kl);
            const float4 f = gfb[(size_t)ik * 16 + rlane];
            const uint32_t h0 = pkbf2(f.x, f.y);
            const uint32_t h1 = pkbf2(f.z, f.w);
            const __nv_bfloat162 hh0 = *(const __nv_bfloat162*)&h0;
            const __nv_bfloat162 hh1 = *(const __nv_bfloat162*)&h1;
            const uint32_t l0 = pkbf2(f.x - __bfloat162float(hh0.x),
                                      f.y - __bfloat162float(hh0.y));
            const uint32_t l1 = pkbf2(f.z - __bfloat162float(hh1.x),
                                      f.w - __bfloat162float(hh1.y));
            *(uint2*)&sFh[kl * FSTR + rlane * 4] = make_uint2(h0, h1);
            *(uint2*)&sFl[kl * FSTR + rlane * 4] = make_uint2(l0, l1);
        }
        __syncwarp();

        // ---- A frags for this k-chunk + B frags, 24 mma
        uint32_t ah[4], al[4];
        const uint32_t aOff = (uint32_t)(aRow * WSTR + kc * 16 + aCol) * 2;
        ldsm4(ah[0], ah[1], ah[2], ah[3], smem_u32(sWh) + aOff);
        ldsm4(al[0], al[1], al[2], al[3], smem_u32(sWl) + aOff);
        #pragma unroll
        for (int g = 0; g < 4; ++g) {                // n in 16-wide groups
            const uint32_t bOff = (uint32_t)(bRow * FSTR + g * 16 + bCol) * 2;
            uint32_t bh[4], bl[4];
            ldsm4t(bh[0], bh[1], bh[2], bh[3], smem_u32(sFh) + bOff);
            ldsm4t(bl[0], bl[1], bl[2], bl[3], smem_u32(sFl) + bOff);
            #pragma unroll
            for (int half = 0; half < 2; ++half) {
                const int nt = 2 * g + half;
                mma_bf16(acc[nt], ah, bh + 2 * half);
                mma_bf16(acc[nt], al, bh + 2 * half);
                mma_bf16(acc[nt], ah, bl + 2 * half);
            }
        }
        __syncwarp();          // frags in regs; safe to overwrite buffer
    }

    // ---- epilogue: stage [p][64] as fp16 hi/lo into reused sFh/sFl, then
    // coalesced uint4 copy of the 960-elem row (120 uint4) to gmem.
    __half* eFh = (__half*)sFh;
    __half* eFl = (__half*)sFl;
    const int r  = lane >> 2;
    const int cb = 2 * (lane & 3);
    #pragma unroll
    for (int nt = 0; nt < 8; ++nt) {
        const int d0 = nt * 8 + cb;
        {   // p = r (0..7)
            const uint32_t h01 = pkhf2(acc[nt][0], acc[nt][1]);
            const __half2 hp = *(const __half2*)&h01;
            const uint32_t l01 = pkhf2(acc[nt][0] - __half2float(hp.x),
                                       acc[nt][1] - __half2float(hp.y));
            *(uint32_t*)&eFh[r * 64 + d0] = h01;
            *(uint32_t*)&eFl[r * 64 + d0] = l01;
        }
        {   // p = r+8 (8..15; row 15 staged but never copied out)
            const uint32_t h23 = pkhf2(acc[nt][2], acc[nt][3]);
            const __half2 hp = *(const __half2*)&h23;
            const uint32_t l23 = pkhf2(acc[nt][2] - __half2float(hp.x),
                                       acc[nt][3] - __half2float(hp.y));
            *(uint32_t*)&eFh[(r + 8) * 64 + d0] = h23;
            *(uint32_t*)&eFl[(r + 8) * 64 + d0] = l23;
        }
    }
    __syncwarp();

    {
        const uint4* eh = (const uint4*)eFh;
        const uint4* el = (const uint4*)eFl;
        uint4* wh = (uint4*)(g_ahi + (size_t)bm * KTOT);
        uint4* wl = (uint4*)(g_alo + (size_t)bm * KTOT);
        #pragma unroll
        for (int i = 0; i < 4; ++i) {
            const int e = lane + i * 32;      // 0..127, need 0..119
            if (e < 120) { wh[e] = eh[e]; wl[e] = el[e]; }
        }
    }
}

// ---------------------------------------------------------------------------
// Kernel 3: mma.sync fp16 GEMM, 2-term A-split, cp.async double buffer.
//   C[128x128] per CTA = (Ahi+Alo)[128x960] @ Wfp16[960x128]; BK=32.
//   R6 skeleton (256 thr, warp tile 32x64), 3 smem arrays instead of 4.
// ---------------------------------------------------------------------------
#define BK    32
#define LDS_  40                 // row stride (elements): 80B, ldsm conflict-free
#define ARR_BYTES  (128 * LDS_ * 2)          // 10240 B per array
#define STAGE_BYTES (3 * ARR_BYTES)          // Ahi, Alo, B = 30720 B
#define GEMM_SMEM  (2 * STAGE_BYTES)         // 61440 B

__global__ __launch_bounds__(256)
void kpconv_mma_gemm(float* __restrict__ out)
{
    extern __shared__ __align__(16) char sm[];
    const uint32_t smem_base = smem_u32(sm);

    const int tid  = threadIdx.x;
    const int wid  = tid >> 5, lane = tid & 31;
    const int wm   = wid & 3;        // warp m-offset: wm*32
    const int wn   = wid >> 2;       // warp n-offset: wn*64
    const size_t rowBase = (size_t)blockIdx.x * 128;

    auto issue_chunk = [&](int c, int stage) {
        const uint32_t sb = smem_base + stage * STAGE_BYTES;
        #pragma unroll
        for (int i = 0; i < 6; ++i) {
            const int idx = tid + i * 256;      // 0..1535
            const int arr = idx >> 9;           // 0..2
            const int rem = idx & 511;
            const int row = rem >> 2, seg = rem & 3;
            const uint32_t dst = sb + arr * ARR_BYTES + (row * LDS_ + seg * 8) * 2;
            const __half* src;
            if (arr == 0)      src = g_ahi + (rowBase + row) * KTOT + c * BK + seg * 8;
            else if (arr == 1) src = g_alo + (rowBase + row) * KTOT + c * BK + seg * 8;
            else               src = g_bh + (size_t)row * KTOT + c * BK + seg * 8;
            cpasync16(dst, src);
        }
        cp_commit();
    };

    float acc[2][8][4];
    #pragma unroll
    for (int i = 0; i < 2; i++)
        #pragma unroll
        for (int j = 0; j < 8; j++)
            #pragma unroll
            for (int q = 0; q < 4; q++) acc[i][j][q] = 0.0f;

    // per-lane ldmatrix row/col patterns
    const int ltile = lane >> 3, lr = lane & 7;
    const int aRow = (ltile & 1) * 8 + lr;
    const int aCol = (ltile >> 1) * 8;
    const int bRow = (ltile >> 1) * 8 + lr;
    const int bCol = (ltile & 1) * 8;

    issue_chunk(0, 0);

    for (int c = 0; c < KTOT / BK; ++c) {
        if (c + 1 < KTOT / BK) { issue_chunk(c + 1, (c + 1) & 1); cp_wait1(); }
        else                   { cp_wait0(); }
        __syncthreads();

        const uint32_t sb  = smem_base + (c & 1) * STAGE_BYTES;
        const uint32_t pAh = sb;
        const uint32_t pAl = sb + ARR_BYTES;
        const uint32_t pB  = sb + 2 * ARR_BYTES;

        #pragma unroll
        for (int kk = 0; kk < 2; ++kk) {
            const int kcol = kk * 16;
            uint32_t afh[2][4], afl[2][4];
            #pragma unroll
            for (int mt = 0; mt < 2; ++mt) {
                const int row = wm * 32 + mt * 16 + aRow;
                const int col = kcol + aCol;
                const uint32_t off = (uint32_t)(row * LDS_ + col) * 2;
                ldsm4(afh[mt][0], afh[mt][1], afh[mt][2], afh[mt][3], pAh + off);
                ldsm4(afl[mt][0], afl[mt][1], afl[mt][2], afl[mt][3], pAl + off);
            }
            #pragma unroll
            for (int g = 0; g < 4; ++g) {
                const int row = wn * 64 + g * 16 + bRow;
                const int col = kcol + bCol;
                const uint32_t off = (uint32_t)(row * LDS_ + col) * 2;
                uint32_t bf[4];
                ldsm4(bf[0], bf[1], bf[2], bf[3], pB + off);
                #pragma unroll
                for (int half = 0; half < 2; ++half) {
                    const int nt = 2 * g + half;
                    #pragma unroll
                    for (int mt = 0; mt < 2; ++mt) {
                        mma_f16(acc[mt][nt], afh[mt], bf + 2 * half);
                        mma_f16(acc[mt][nt], afl[mt], bf + 2 * half);
                    }
                }
            }
        }
        __syncthreads();
    }

    // epilogue: c0:(r,c) c1:(r,c+1) c2:(r+8,c) c3:(r+8,c+1)
    const int bb     = (int)(rowBase >> 14);
    const int mLocal = (int)(rowBase & 16383);
    #pragma unroll
    for (int mt = 0; mt < 2; ++mt)
        #pragma unroll
        for (int nt = 0; nt < 8; ++nt) {
            const int m0 = mLocal + wm * 32 + mt * 16 + (lane >> 2);
            const int n0 = wn * 64 + nt * 8 + 2 * (lane & 3);
            float* o0 = out + ((size_t)bb * DOUT_ + n0) * M_ + m0;
            o0[0]      = acc[mt][nt][0];
            o0[M_]     = acc[mt][nt][1];
            o0[8]      = acc[mt][nt][2];
            o0[M_ + 8] = acc[mt][nt][3];
        }
}

// ---------------------------------------------------------------------------
extern "C" void kernel_launch(void* const* d_in, const int* in_sizes, int n_in,
                              void* d_out, int out_size)
{
    // Dispatch inputs by (pairwise-distinct) element count:
    const float* points_xyz    = nullptr;
    const float* features      = nullptr;
    const float* center_xyz    = nullptr;
    const int*   neighbor_idx  = nullptr;
    const float* kernel_points = nullptr;
    const float* weights       = nullptr;

    for (int i = 0; i < n_in; i++) {
        switch (in_sizes[i]) {
            case 393216:  points_xyz    = (const float*)d_in[i]; break;
            case 8388608: features      = (const float*)d_in[i]; break;
            case 98304:   center_xyz    = (const float*)d_in[i]; break;
            case 1048576: neighbor_idx  = (const int*)d_in[i];   break;
            case 45:      kernel_points = (const float*)d_in[i]; break;
            case 122880:  weights       = (const float*)d_in[i]; break;
            default: break;
        }
    }
    float* out = (float*)d_out;

    cudaFuncSetAttribute(kpconv_mma_gemm,
                         cudaFuncAttributeMaxDynamicSharedMemorySize, GEMM_SMEM);
    cudaFuncSetAttribute(kpconv_weighted_mma,
                         cudaFuncAttributeMaxDynamicSharedMemorySize, K2_SMEM);

    dim3 g1(N_ / 32, DIN_ / 32, B_);
    transpose_feat_kernel<<<g1, dim3(32, 8)>>>(features);

    prep_w_kernel<<<(KP_ * DIN_ * DOUT_ + 255) / 256, 256>>>(weights);

    kpconv_weighted_mma<<<(B_ * M_) / PTS2, 256, K2_SMEM>>>(
        points_xyz, center_xyz, neighbor_idx, kernel_points);

    kpconv_mma_gemm<<<(B_ * M_) / 128, 256, GEMM_SMEM>>>(out);
}

// round 14
// speedup vs baseline: 1.3027x; 1.0759x over previous
#include <cuda_runtime.h>
#include <cuda_bf16.h>
#include <cuda_fp16.h>
#include <stdint.h>

#define B_     2
#define N_     65536
#define M_     16384
#define K_     32
#define KP_    15
#define DIN_   64
#define DOUT_  128
#define KTOT   960           // KP_*DIN_
#define SHADOW (-1000.0f)

// ---------------------------------------------------------------------------
// Scratch (__device__ globals per no-allocation rule)
// ---------------------------------------------------------------------------
__device__ __align__(16) __half g_featTh[(size_t)B_ * N_ * DIN_];  // 16.8 MB fp16
__device__ __align__(16) __half g_ahi[(size_t)B_ * M_ * KTOT];     // 60 MB (A hi)
__device__ __align__(16) __half g_alo[(size_t)B_ * M_ * KTOT];     // 60 MB (A lo)
__device__ __align__(16) __half g_bh[DOUT_ * KTOT];                // W^T fp16

// ---------------------------------------------------------------------------
// helpers
// ---------------------------------------------------------------------------
__device__ __forceinline__ uint32_t smem_u32(const void* p) {
    uint32_t a;
    asm("{ .reg .u64 t; cvta.to.shared.u64 t, %1; cvt.u32.u64 %0, t; }"
        : "=r"(a) : "l"(p));
    return a;
}
__device__ __forceinline__ void ldsm4(uint32_t& r0, uint32_t& r1,
                                      uint32_t& r2, uint32_t& r3, uint32_t addr) {
    asm volatile("ldmatrix.sync.aligned.m8n8.x4.shared.b16 {%0,%1,%2,%3}, [%4];"
                 : "=r"(r0), "=r"(r1), "=r"(r2), "=r"(r3) : "r"(addr));
}
__device__ __forceinline__ void ldsm4t(uint32_t& r0, uint32_t& r1,
                                       uint32_t& r2, uint32_t& r3, uint32_t addr) {
    asm volatile("ldmatrix.sync.aligned.m8n8.x4.trans.shared.b16 {%0,%1,%2,%3}, [%4];"
                 : "=r"(r0), "=r"(r1), "=r"(r2), "=r"(r3) : "r"(addr));
}
__device__ __forceinline__ void mma_f16(float* c, const uint32_t* a,
                                        const uint32_t* b) {
    asm volatile("mma.sync.aligned.m16n8k16.row.col.f32.f16.f16.f32 "
                 "{%0,%1,%2,%3}, {%4,%5,%6,%7}, {%8,%9}, {%0,%1,%2,%3};"
                 : "+f"(c[0]), "+f"(c[1]), "+f"(c[2]), "+f"(c[3])
                 : "r"(a[0]), "r"(a[1]), "r"(a[2]), "r"(a[3]),
                   "r"(b[0]), "r"(b[1]));
}
__device__ __forceinline__ void cpasync16(uint32_t dst, const void* src) {
    asm volatile("cp.async.ca.shared.global [%0], [%1], 16;" :: "r"(dst), "l"(src));
}
__device__ __forceinline__ void cp_commit() {
    asm volatile("cp.async.commit_group;" ::: "memory");
}
__device__ __forceinline__ void cp_wait1() {
    asm volatile("cp.async.wait_group 1;" ::: "memory");
}
__device__ __forceinline__ void cp_wait0() {
    asm volatile("cp.async.wait_group 0;" ::: "memory");
}
__device__ __forceinline__ uint32_t pkhf2(float a, float b) {
    __half2 t = __floats2half2_rn(a, b);
    return *(uint32_t*)&t;
}

// ---------------------------------------------------------------------------
// Kernel 1: transpose features [B][Din][N] -> g_featTh [B][N][Din] (fp16)
// ---------------------------------------------------------------------------
__global__ void transpose_feat_kernel(const float* __restrict__ f)
{
    __shared__ float tile[32][33];
    const int b  = blockIdx.z;
    const int n0 = blockIdx.x * 32;
    const int d0 = blockIdx.y * 32;
    const int x = threadIdx.x, y = threadIdx.y;

    #pragma unroll
    for (int i = y; i < 32; i += 8)
        tile[i][x] = f[((size_t)b * DIN_ + (d0 + i)) * N_ + n0 + x];
    __syncthreads();
    #pragma unroll
    for (int i = y; i < 32; i += 8)
        g_featTh[((size_t)b * N_ + (n0 + i)) * DIN_ + d0 + x] =
            __float2half_rn(tile[x][i]);
}

// ---------------------------------------------------------------------------
// Kernel 1b: weights [Kp][Din][Dout] -> g_bh [Dout rows][KTOT cols] (fp16)
// ---------------------------------------------------------------------------
__global__ void prep_w_kernel(const float* __restrict__ w)
{
    const int e = blockIdx.x * 256 + threadIdx.x;
    if (e >= KP_ * DIN_ * DOUT_) return;
    const int kp = e / DOUT_, o = e % DOUT_;
    g_bh[o * KTOT + kp] = __float2half_rn(w[e]);
}

// ---------------------------------------------------------------------------
// Kernel 2: einsum1 on tensor cores, fp16 2-term (w hi/lo x feat single).
//   warp <-> point; 8 points / 256-thr CTA; 16-row chunked F buffer.
//   Gather = pure uint4 copies from fp16 featT (no conversions).
// NOTE: neighbor_indices is int32 (JAX canonicalizes int64 -> int32).
// ---------------------------------------------------------------------------
#define PTS2   8
#define FSTR   72                        // feat smem row stride (fp16 elems)
#define WSTR   40                        // w smem row stride (fp16 elems)
#define F_BYTES (16 * FSTR * 2)          // 2304 (single fp16 chunk buffer)
#define W_BYTES (16 * WSTR * 2)          // 1280
#define PT_BYTES (F_BYTES + 2 * W_BYTES) // 4864
#define K2_SMEM (PTS2 * PT_BYTES)        // 38912

__global__ __launch_bounds__(256)
void kpconv_weighted_mma(const float* __restrict__ points_xyz,
                         const float* __restrict__ center_xyz,
                         const int* __restrict__ nidx,
                         const float* __restrict__ kernel_points)
{
    extern __shared__ __align__(16) char k2sm[];
    const int wpt  = threadIdx.x >> 5;   // warp id == local point id
    const int lane = threadIdx.x & 31;
    const int bm   = blockIdx.x * PTS2 + wpt;
    const int b    = bm >> 14;

    __half* sF  = (__half*)(k2sm + wpt * PT_BYTES);
    __half* sWh = sF + 16 * FSTR;
    __half* sWl = sWh + 16 * WSTR;

    // ---- phase 1: lane = k; coords in registers
    const int ii0 = nidx[(size_t)bm * K_ + lane];
    const bool valid = (unsigned)ii0 < (unsigned)N_;
    const int idx = valid ? ii0 : 0;
    float px = SHADOW, py = SHADOW, pz = SHADOW;
    if (valid) {
        const float* pp = points_xyz + ((size_t)b * N_ + ii0) * 3;
        px = pp[0]; py = pp[1]; pz = pp[2];
    }
    const float rx = px - center_xyz[bm * 3 + 0];
    const float ry = py - center_xyz[bm * 3 + 1];
    const float rz = pz - center_xyz[bm * 3 + 2];
    float md = sqrtf(rx * rx + ry * ry + rz * rz);
    #pragma unroll
    for (int o = 16; o; o >>= 1)
        md = fmaxf(md, __shfl_xor_sync(0xffffffffu, md, o));
    const float inv = 1.0f / (md / 2.1f + 1e-5f);

    // ---- phase 2: w[p] -> A smem [p][k=lane], fp16 hi/lo; row 15 zero
    #pragma unroll
    for (int p = 0; p < KP_; ++p) {
        const float kx = kernel_points[p * 3 + 0] * md;
        const float ky = kernel_points[p * 3 + 1] * md;
        const float kz = kernel_points[p * 3 + 2] * md;
        const float dx = rx - kx, dy = ry - ky, dz = rz - kz;
        float w = 1.0f - sqrtf(dx * dx + dy * dy + dz * dz) * inv;
        w = valid ? fmaxf(w, 0.0f) : 0.0f;
        const __half h = __float2half_rn(w);
        sWh[p * WSTR + lane] = h;
        sWl[p * WSTR + lane] = __float2half_rn(w - __half2float(h));
    }
    sWh[15 * WSTR + lane] = __float2half_rn(0.0f);
    sWl[15 * WSTR + lane] = __float2half_rn(0.0f);

    float acc[8][4];
    #pragma unroll
    for (int j = 0; j < 8; ++j)
        #pragma unroll
        for (int q = 0; q < 4; ++q) acc[j][q] = 0.0f;

    const int ltile = lane >> 3, lr = lane & 7;
    const int aRow = (ltile & 1) * 8 + lr;
    const int aCol = (ltile >> 1) * 8;
    const int bRow = (ltile & 1) * 8 + lr;
    const int bCol = (ltile >> 1) * 8;
    const int grow = lane >> 3;           // row within 4-row gather group
    const int gseg = lane & 7;            // uint4 slot within 128B row
    const uint4* gfb = (const uint4*)(g_featTh + (size_t)b * N_ * DIN_);

    #pragma unroll
    for (int kc = 0; kc < 2; ++kc) {
        // ---- gather 16 fp16 feat rows: pure uint4 copy, 4 rows per pass
        #pragma unroll
        for (int pass = 0; pass < 4; ++pass) {
            const int kl = pass * 4 + grow;          // local row 0..15
            const int ik = __shfl_sync(0xffffffffu, idx, kc * 16 + kl);
            *(uint4*)&sF[kl * FSTR + gseg * 8] = gfb[(size_t)ik * 8 + gseg];
        }
        __syncwarp();

        // ---- A frags (w hi/lo) + B frags (feat), 16 mma per chunk
        uint32_t ah[4], al[4];
        const uint32_t aOff = (uint32_t)(aRow * WSTR + kc * 16 + aCol) * 2;
        ldsm4(ah[0], ah[1], ah[2], ah[3], smem_u32(sWh) + aOff);
        ldsm4(al[0], al[1], al[2], al[3], smem_u32(sWl) + aOff);
        #pragma unroll
        for (int g = 0; g < 4; ++g) {                // n in 16-wide groups
            const uint32_t bOff = (uint32_t)(bRow * FSTR + g * 16 + bCol) * 2;
            uint32_t bf[4];
            ldsm4t(bf[0], bf[1], bf[2], bf[3], smem_u32(sF) + bOff);
            #pragma unroll
            for (int half = 0; half < 2; ++half) {
                const int nt = 2 * g + half;
                mma_f16(acc[nt], ah, bf + 2 * half);
                mma_f16(acc[nt], al, bf + 2 * half);
            }
        }
        __syncwarp();          // frags in regs; safe to overwrite buffer
    }

    // ---- epilogue: stage [p][64] fp16 hi into sF, lo into sWh/sWl region,
    // then coalesced uint4 copy (120 uint4 each) to gmem.
    __half* eFh = sF;                     // 2048 B needed, 2304 available
    __half* eFl = sWh;                    // 2048 B needed, 2560 available
    const int r  = lane >> 2;
    const int cb = 2 * (lane & 3);
    #pragma unroll
    for (int nt = 0; nt < 8; ++nt) {
        const int d0 = nt * 8 + cb;
        {   // p = r (0..7)
            const uint32_t h01 = pkhf2(acc[nt][0], acc[nt][1]);
            const __half2 hp = *(const __half2*)&h01;
            const uint32_t l01 = pkhf2(acc[nt][0] - __half2float(hp.x),
                                       acc[nt][1] - __half2float(hp.y));
            *(uint32_t*)&eFh[r * 64 + d0] = h01;
            *(uint32_t*)&eFl[r * 64 + d0] = l01;
        }
        {   // p = r+8 (8..15; row 15 staged but never copied out)
            const uint32_t h23 = pkhf2(acc[nt][2], acc[nt][3]);
            const __half2 hp = *(const __half2*)&h23;
            const uint32_t l23 = pkhf2(acc[nt][2] - __half2float(hp.x),
                                       acc[nt][3] - __half2float(hp.y));
            *(uint32_t*)&eFh[(r + 8) * 64 + d0] = h23;
            *(uint32_t*)&eFl[(r + 8) * 64 + d0] = l23;
        }
    }
    __syncwarp();

    {
        const uint4* eh = (const uint4*)eFh;
        const uint4* el = (const uint4*)eFl;
        uint4* wh = (uint4*)(g_ahi + (size_t)bm * KTOT);
        uint4* wl = (uint4*)(g_alo + (size_t)bm * KTOT);
        #pragma unroll
        for (int i = 0; i < 4; ++i) {
            const int e = lane + i * 32;      // 0..127, need 0..119
            if (e < 120) { wh[e] = eh[e]; wl[e] = el[e]; }
        }
    }
}

// ---------------------------------------------------------------------------
// Kernel 3: mma.sync fp16 GEMM, 2-term A-split, cp.async double buffer.
//   (exact R13 configuration — measured 52.5 us)
// ---------------------------------------------------------------------------
#define BK    32
#define LDS_  40                 // row stride (elements): 80B, ldsm conflict-free
#define ARR_BYTES  (128 * LDS_ * 2)          // 10240 B per array
#define STAGE_BYTES (3 * ARR_BYTES)          // Ahi, Alo, B = 30720 B
#define GEMM_SMEM  (2 * STAGE_BYTES)         // 61440 B

__global__ __launch_bounds__(256)
void kpconv_mma_gemm(float* __restrict__ out)
{
    extern __shared__ __align__(16) char sm[];
    const uint32_t smem_base = smem_u32(sm);

    const int tid  = threadIdx.x;
    const int wid  = tid >> 5, lane = tid & 31;
    const int wm   = wid & 3;        // warp m-offset: wm*32
    const int wn   = wid >> 2;       // warp n-offset: wn*64
    const size_t rowBase = (size_t)blockIdx.x * 128;

    auto issue_chunk = [&](int c, int stage) {
        const uint32_t sb = smem_base + stage * STAGE_BYTES;
        #pragma unroll
        for (int i = 0; i < 6; ++i) {
            const int idx = tid + i * 256;      // 0..1535
            const int arr = idx >> 9;           // 0..2
            const int rem = idx & 511;
            const int row = rem >> 2, seg = rem & 3;
            const uint32_t dst = sb + arr * ARR_BYTES + (row * LDS_ + seg * 8) * 2;
            const __half* src;
            if (arr == 0)      src = g_ahi + (rowBase + row) * KTOT + c * BK + seg * 8;
            else if (arr == 1) src = g_alo + (rowBase + row) * KTOT + c * BK + seg * 8;
            else               src = g_bh + (size_t)row * KTOT + c * BK + seg * 8;
            cpasync16(dst, src);
        }
        cp_commit();
    };

    float acc[2][8][4];
    #pragma unroll
    for (int i = 0; i < 2; i++)
        #pragma unroll
        for (int j = 0; j < 8; j++)
            #pragma unroll
            for (int q = 0; q < 4; q++) acc[i][j][q] = 0.0f;

    // per-lane ldmatrix row/col patterns
    const int ltile = lane >> 3, lr = lane & 7;
    const int aRow = (ltile & 1) * 8 + lr;
    const int aCol = (ltile >> 1) * 8;
    const int bRow = (ltile >> 1) * 8 + lr;
    const int bCol = (ltile & 1) * 8;

    issue_chunk(0, 0);

    for (int c = 0; c < KTOT / BK; ++c) {
        if (c + 1 < KTOT / BK) { issue_chunk(c + 1, (c + 1) & 1); cp_wait1(); }
        else                   { cp_wait0(); }
        __syncthreads();

        const uint32_t sb  = smem_base + (c & 1) * STAGE_BYTES;
        const uint32_t pAh = sb;
        const uint32_t pAl = sb + ARR_BYTES;
        const uint32_t pB  = sb + 2 * ARR_BYTES;

        #pragma unroll
        for (int kk = 0; kk < 2; ++kk) {
            const int kcol = kk * 16;
            uint32_t afh[2][4], afl[2][4];
            #pragma unroll
            for (int mt = 0; mt < 2; ++mt) {
                const int row = wm * 32 + mt * 16 + aRow;
                const int col = kcol + aCol;
                const uint32_t off = (uint32_t)(row * LDS_ + col) * 2;
                ldsm4(afh[mt][0], afh[mt][1], afh[mt][2], afh[mt][3], pAh + off);
                ldsm4(afl[mt][0], afl[mt][1], afl[mt][2], afl[mt][3], pAl + off);
            }
            #pragma unroll
            for (int g = 0; g < 4; ++g) {
                const int row = wn * 64 + g * 16 + bRow;
                const int col = kcol + bCol;
                const uint32_t off = (uint32_t)(row * LDS_ + col) * 2;
                uint32_t bf[4];
                ldsm4(bf[0], bf[1], bf[2], bf[3], pB + off);
                #pragma unroll
                for (int half = 0; half < 2; ++half) {
                    const int nt = 2 * g + half;
                    #pragma unroll
                    for (int mt = 0; mt < 2; ++mt) {
                        mma_f16(acc[mt][nt], afh[mt], bf + 2 * half);
                        mma_f16(acc[mt][nt], afl[mt], bf + 2 * half);
                    }
                }
            }
        }
        __syncthreads();
    }

    // epilogue: c0:(r,c) c1:(r,c+1) c2:(r+8,c) c3:(r+8,c+1)
    const int bb     = (int)(rowBase >> 14);
    const int mLocal = (int)(rowBase & 16383);
    #pragma unroll
    for (int mt = 0; mt < 2; ++mt)
        #pragma unroll
        for (int nt = 0; nt < 8; ++nt) {
            const int m0 = mLocal + wm * 32 + mt * 16 + (lane >> 2);
            const int n0 = wn * 64 + nt * 8 + 2 * (lane & 3);
            float* o0 = out + ((size_t)bb * DOUT_ + n0) * M_ + m0;
            o0[0]      = acc[mt][nt][0];
            o0[M_]     = acc[mt][nt][1];
            o0[8]      = acc[mt][nt][2];
            o0[M_ + 8] = acc[mt][nt][3];
        }
}

// ---------------------------------------------------------------------------
extern "C" void kernel_launch(void* const* d_in, const int* in_sizes, int n_in,
                              void* d_out, int out_size)
{
    // Dispatch inputs by (pairwise-distinct) element count:
    const float* points_xyz    = nullptr;
    const float* features      = nullptr;
    const float* center_xyz    = nullptr;
    const int*   neighbor_idx  = nullptr;
    const float* kernel_points = nullptr;
    const float* weights       = nullptr;

    for (int i = 0; i < n_in; i++) {
        switch (in_sizes[i]) {
            case 393216:  points_xyz    = (const float*)d_in[i]; break;
            case 8388608: features      = (const float*)d_in[i]; break;
            case 98304:   center_xyz    = (const float*)d_in[i]; break;
            case 1048576: neighbor_idx  = (const int*)d_in[i];   break;
            case 45:      kernel_points = (const float*)d_in[i]; break;
            case 122880:  weights       = (const float*)d_in[i]; break;
            default: break;
        }
    }
    float* out = (float*)d_out;

    cudaFuncSetAttribute(kpconv_mma_gemm,
                         cudaFuncAttributeMaxDynamicSharedMemorySize, GEMM_SMEM);
    cudaFuncSetAttribute(kpconv_weighted_mma,
                         cudaFuncAttributeMaxDynamicSharedMemorySize, K2_SMEM);
    cudaFuncSetAttribute(kpconv_weighted_mma,
                         cudaFuncAttributePreferredSharedMemoryCarveout, 100);

    dim3 g1(N_ / 32, DIN_ / 32, B_);
    transpose_feat_kernel<<<g1, dim3(32, 8)>>>(features);

    prep_w_kernel<<<(KP_ * DIN_ * DOUT_ + 255) / 256, 256>>>(weights);

    kpconv_weighted_mma<<<(B_ * M_) / PTS2, 256, K2_SMEM>>>(
        points_xyz, center_xyz, neighbor_idx, kernel_points);

    kpconv_mma_gemm<<<(B_ * M_) / 128, 256, GEMM_SMEM>>>(out);
}

// round 15
// speedup vs baseline: 1.6555x; 1.2708x over previous
#include <cuda_runtime.h>
#include <cuda_bf16.h>
#include <cuda_fp16.h>
#include <stdint.h>

#define B_     2
#define N_     65536
#define M_     16384
#define K_     32
#define KP_    15
#define DIN_   64
#define DOUT_  128
#define KTOT   960           // KP_*DIN_
#define SHADOW (-1000.0f)

// ---------------------------------------------------------------------------
// Scratch (__device__ globals per no-allocation rule)
// ---------------------------------------------------------------------------
__device__ __align__(16) __half g_featTh[(size_t)B_ * N_ * DIN_];  // 16.8 MB fp16
__device__ __align__(16) __half g_a[(size_t)B_ * M_ * KTOT];       // 60 MB (A fp16)
__device__ __align__(16) __half g_bh[DOUT_ * KTOT];                // W^T fp16

// ---------------------------------------------------------------------------
// helpers
// ---------------------------------------------------------------------------
__device__ __forceinline__ uint32_t smem_u32(const void* p) {
    uint32_t a;
    asm("{ .reg .u64 t; cvta.to.shared.u64 t, %1; cvt.u32.u64 %0, t; }"
        : "=r"(a) : "l"(p));
    return a;
}
__device__ __forceinline__ void ldsm4(uint32_t& r0, uint32_t& r1,
                                      uint32_t& r2, uint32_t& r3, uint32_t addr) {
    asm volatile("ldmatrix.sync.aligned.m8n8.x4.shared.b16 {%0,%1,%2,%3}, [%4];"
                 : "=r"(r0), "=r"(r1), "=r"(r2), "=r"(r3) : "r"(addr));
}
__device__ __forceinline__ void ldsm4t(uint32_t& r0, uint32_t& r1,
                                       uint32_t& r2, uint32_t& r3, uint32_t addr) {
    asm volatile("ldmatrix.sync.aligned.m8n8.x4.trans.shared.b16 {%0,%1,%2,%3}, [%4];"
                 : "=r"(r0), "=r"(r1), "=r"(r2), "=r"(r3) : "r"(addr));
}
__device__ __forceinline__ void mma_f16(float* c, const uint32_t* a,
                                        const uint32_t* b) {
    asm volatile("mma.sync.aligned.m16n8k16.row.col.f32.f16.f16.f32 "
                 "{%0,%1,%2,%3}, {%4,%5,%6,%7}, {%8,%9}, {%0,%1,%2,%3};"
                 : "+f"(c[0]), "+f"(c[1]), "+f"(c[2]), "+f"(c[3])
                 : "r"(a[0]), "r"(a[1]), "r"(a[2]), "r"(a[3]),
                   "r"(b[0]), "r"(b[1]));
}
__device__ __forceinline__ void cpasync16(uint32_t dst, const void* src) {
    asm volatile("cp.async.ca.shared.global [%0], [%1], 16;" :: "r"(dst), "l"(src));
}
__device__ __forceinline__ void cp_commit() {
    asm volatile("cp.async.commit_group;" ::: "memory");
}
__device__ __forceinline__ void cp_wait1() {
    asm volatile("cp.async.wait_group 1;" ::: "memory");
}
__device__ __forceinline__ void cp_wait0() {
    asm volatile("cp.async.wait_group 0;" ::: "memory");
}
__device__ __forceinline__ uint32_t pkhf2(float a, float b) {
    __half2 t = __floats2half2_rn(a, b);
    return *(uint32_t*)&t;
}

// ---------------------------------------------------------------------------
// Kernel 1: transpose features [B][Din][N] -> g_featTh [B][N][Din] (fp16)
// ---------------------------------------------------------------------------
__global__ void transpose_feat_kernel(const float* __restrict__ f)
{
    __shared__ float tile[32][33];
    const int b  = blockIdx.z;
    const int n0 = blockIdx.x * 32;
    const int d0 = blockIdx.y * 32;
    const int x = threadIdx.x, y = threadIdx.y;

    #pragma unroll
    for (int i = y; i < 32; i += 8)
        tile[i][x] = f[((size_t)b * DIN_ + (d0 + i)) * N_ + n0 + x];
    __syncthreads();
    #pragma unroll
    for (int i = y; i < 32; i += 8)
        g_featTh[((size_t)b * N_ + (n0 + i)) * DIN_ + d0 + x] =
            __float2half_rn(tile[x][i]);
}

// ---------------------------------------------------------------------------
// Kernel 1b: weights [Kp][Din][Dout] -> g_bh [Dout rows][KTOT cols] (fp16)
// ---------------------------------------------------------------------------
__global__ void prep_w_kernel(const float* __restrict__ w)
{
    const int e = blockIdx.x * 256 + threadIdx.x;
    if (e >= KP_ * DIN_ * DOUT_) return;
    const int kp = e / DOUT_, o = e % DOUT_;
    g_bh[o * KTOT + kp] = __float2half_rn(w[e]);
}

// ---------------------------------------------------------------------------
// Kernel 2: einsum1 on tensor cores, fp16 2-term internally (w hi/lo x feat),
//   single-fp16 A output. warp <-> point; 8 points / 256-thr CTA.
// NOTE: neighbor_indices is int32 (JAX canonicalizes int64 -> int32).
// ---------------------------------------------------------------------------
#define PTS2   8
#define FSTR   72                        // feat smem row stride (fp16 elems)
#define WSTR   40                        // w smem row stride (fp16 elems)
#define F_BYTES (16 * FSTR * 2)          // 2304 (single fp16 chunk buffer)
#define W_BYTES (16 * WSTR * 2)          // 1280
#define PT_BYTES (F_BYTES + 2 * W_BYTES) // 4864
#define K2_SMEM (PTS2 * PT_BYTES)        // 38912

__global__ __launch_bounds__(256)
void kpconv_weighted_mma(const float* __restrict__ points_xyz,
                         const float* __restrict__ center_xyz,
                         const int* __restrict__ nidx,
                         const float* __restrict__ kernel_points)
{
    extern __shared__ __align__(16) char k2sm[];
    const int wpt  = threadIdx.x >> 5;   // warp id == local point id
    const int lane = threadIdx.x & 31;
    const int bm   = blockIdx.x * PTS2 + wpt;
    const int b    = bm >> 14;

    __half* sF  = (__half*)(k2sm + wpt * PT_BYTES);
    __half* sWh = sF + 16 * FSTR;
    __half* sWl = sWh + 16 * WSTR;

    // ---- phase 1: lane = k; coords in registers
    const int ii0 = nidx[(size_t)bm * K_ + lane];
    const bool valid = (unsigned)ii0 < (unsigned)N_;
    const int idx = valid ? ii0 : 0;
    float px = SHADOW, py = SHADOW, pz = SHADOW;
    if (valid) {
        const float* pp = points_xyz + ((size_t)b * N_ + ii0) * 3;
        px = pp[0]; py = pp[1]; pz = pp[2];
    }
    const float rx = px - center_xyz[bm * 3 + 0];
    const float ry = py - center_xyz[bm * 3 + 1];
    const float rz = pz - center_xyz[bm * 3 + 2];
    float md = sqrtf(rx * rx + ry * ry + rz * rz);
    #pragma unroll
    for (int o = 16; o; o >>= 1)
        md = fmaxf(md, __shfl_xor_sync(0xffffffffu, md, o));
    const float inv = 1.0f / (md / 2.1f + 1e-5f);

    // ---- phase 2: w[p] -> A smem [p][k=lane], fp16 hi/lo; row 15 zero
    #pragma unroll
    for (int p = 0; p < KP_; ++p) {
        const float kx = kernel_points[p * 3 + 0] * md;
        const float ky = kernel_points[p * 3 + 1] * md;
        const float kz = kernel_points[p * 3 + 2] * md;
        const float dx = rx - kx, dy = ry - ky, dz = rz - kz;
        float w = 1.0f - sqrtf(dx * dx + dy * dy + dz * dz) * inv;
        w = valid ? fmaxf(w, 0.0f) : 0.0f;
        const __half h = __float2half_rn(w);
        sWh[p * WSTR + lane] = h;
        sWl[p * WSTR + lane] = __float2half_rn(w - __half2float(h));
    }
    sWh[15 * WSTR + lane] = __float2half_rn(0.0f);
    sWl[15 * WSTR + lane] = __float2half_rn(0.0f);

    float acc[8][4];
    #pragma unroll
    for (int j = 0; j < 8; ++j)
        #pragma unroll
        for (int q = 0; q < 4; ++q) acc[j][q] = 0.0f;

    const int ltile = lane >> 3, lr = lane & 7;
    const int aRow = (ltile & 1) * 8 + lr;
    const int aCol = (ltile >> 1) * 8;
    const int bRow = (ltile & 1) * 8 + lr;
    const int bCol = (ltile >> 1) * 8;
    const int grow = lane >> 3;           // row within 4-row gather group
    const int gseg = lane & 7;            // uint4 slot within 128B row
    const uint4* gfb = (const uint4*)(g_featTh + (size_t)b * N_ * DIN_);

    #pragma unroll
    for (int kc = 0; kc < 2; ++kc) {
        // ---- gather 16 fp16 feat rows: pure uint4 copy, 4 rows per pass
        #pragma unroll
        for (int pass = 0; pass < 4; ++pass) {
            const int kl = pass * 4 + grow;          // local row 0..15
            const int ik = __shfl_sync(0xffffffffu, idx, kc * 16 + kl);
            *(uint4*)&sF[kl * FSTR + gseg * 8] = gfb[(size_t)ik * 8 + gseg];
        }
        __syncwarp();

        // ---- A frags (w hi/lo) + B frags (feat), 16 mma per chunk
        uint32_t ah[4], al[4];
        const uint32_t aOff = (uint32_t)(aRow * WSTR + kc * 16 + aCol) * 2;
        ldsm4(ah[0], ah[1], ah[2], ah[3], smem_u32(sWh) + aOff);
        ldsm4(al[0], al[1], al[2], al[3], smem_u32(sWl) + aOff);
        #pragma unroll
        for (int g = 0; g < 4; ++g) {                // n in 16-wide groups
            const uint32_t bOff = (uint32_t)(bRow * FSTR + g * 16 + bCol) * 2;
            uint32_t bf[4];
            ldsm4t(bf[0], bf[1], bf[2], bf[3], smem_u32(sF) + bOff);
            #pragma unroll
            for (int half = 0; half < 2; ++half) {
                const int nt = 2 * g + half;
                mma_f16(acc[nt], ah, bf + 2 * half);
                mma_f16(acc[nt], al, bf + 2 * half);
            }
        }
        __syncwarp();          // frags in regs; safe to overwrite buffer
    }

    // ---- epilogue: stage [p][64] fp16 into sF, then coalesced uint4 copy
    // (120 uint4) to gmem.
    __half* eF = sF;                      // 2048 B needed, 2304 available
    const int r  = lane >> 2;
    const int cb = 2 * (lane & 3);
    #pragma unroll
    for (int nt = 0; nt < 8; ++nt) {
        const int d0 = nt * 8 + cb;
        *(uint32_t*)&eF[r * 64 + d0]       = pkhf2(acc[nt][0], acc[nt][1]);
        // p = r+8 (8..15; row 15 staged but never copied out)
        *(uint32_t*)&eF[(r + 8) * 64 + d0] = pkhf2(acc[nt][2], acc[nt][3]);
    }
    __syncwarp();

    {
        const uint4* eh = (const uint4*)eF;
        uint4* wh = (uint4*)(g_a + (size_t)bm * KTOT);
        #pragma unroll
        for (int i = 0; i < 4; ++i) {
            const int e = lane + i * 32;      // 0..127, need 0..119
            if (e < 120) wh[e] = eh[e];
        }
    }
}

// ---------------------------------------------------------------------------
// Kernel 3: mma.sync fp16 GEMM, single-term, cp.async double buffer.
//   C[128x128] per CTA = A[128x960] @ Wfp16[960x128]; BK=32.
// ---------------------------------------------------------------------------
#define BK    32
#define LDS_  40                 // row stride (elements): 80B, ldsm conflict-free
#define ARR_BYTES  (128 * LDS_ * 2)          // 10240 B per array
#define STAGE_BYTES (2 * ARR_BYTES)          // A, B = 20480 B
#define GEMM_SMEM  (2 * STAGE_BYTES)         // 40960 B

__global__ __launch_bounds__(256)
void kpconv_mma_gemm(float* __restrict__ out)
{
    extern __shared__ __align__(16) char sm[];
    const uint32_t smem_base = smem_u32(sm);

    const int tid  = threadIdx.x;
    const int wid  = tid >> 5, lane = tid & 31;
    const int wm   = wid & 3;        // warp m-offset: wm*32
    const int wn   = wid >> 2;       // warp n-offset: wn*64
    const size_t rowBase = (size_t)blockIdx.x * 128;

    auto issue_chunk = [&](int c, int stage) {
        const uint32_t sb = smem_base + stage * STAGE_BYTES;
        #pragma unroll
        for (int i = 0; i < 4; ++i) {
            const int idx = tid + i * 256;      // 0..1023
            const int arr = idx >> 9;           // 0..1
            const int rem = idx & 511;
            const int row = rem >> 2, seg = rem & 3;
            const uint32_t dst = sb + arr * ARR_BYTES + (row * LDS_ + seg * 8) * 2;
            const __half* src;
            if (arr == 0) src = g_a  + (rowBase + row) * KTOT + c * BK + seg * 8;
            else          src = g_bh + (size_t)row * KTOT + c * BK + seg * 8;
            cpasync16(dst, src);
        }
        cp_commit();
    };

    float acc[2][8][4];
    #pragma unroll
    for (int i = 0; i < 2; i++)
        #pragma unroll
        for (int j = 0; j < 8; j++)
            #pragma unroll
            for (int q = 0; q < 4; q++) acc[i][j][q] = 0.0f;

    // per-lane ldmatrix row/col patterns
    const int ltile = lane >> 3, lr = lane & 7;
    const int aRow = (ltile & 1) * 8 + lr;
    const int aCol = (ltile >> 1) * 8;
    const int bRow = (ltile >> 1) * 8 + lr;
    const int bCol = (ltile & 1) * 8;

    issue_chunk(0, 0);

    for (int c = 0; c < KTOT / BK; ++c) {
        if (c + 1 < KTOT / BK) { issue_chunk(c + 1, (c + 1) & 1); cp_wait1(); }
        else                   { cp_wait0(); }
        __syncthreads();

        const uint32_t sb = smem_base + (c & 1) * STAGE_BYTES;
        const uint32_t pA = sb;
        const uint32_t pB = sb + ARR_BYTES;

        #pragma unroll
        for (int kk = 0; kk < 2; ++kk) {
            const int kcol = kk * 16;
            uint32_t af[2][4];
            #pragma unroll
            for (int mt = 0; mt < 2; ++mt) {
                const int row = wm * 32 + mt * 16 + aRow;
                const int col = kcol + aCol;
                const uint32_t off = (uint32_t)(row * LDS_ + col) * 2;
                ldsm4(af[mt][0], af[mt][1], af[mt][2], af[mt][3], pA + off);
            }
            #pragma unroll
            for (int g = 0; g < 4; ++g) {
                const int row = wn * 64 + g * 16 + bRow;
                const int col = kcol + bCol;
                const uint32_t off = (uint32_t)(row * LDS_ + col) * 2;
                uint32_t bf[4];
                ldsm4(bf[0], bf[1], bf[2], bf[3], pB + off);
                #pragma unroll
                for (int half = 0; half < 2; ++half) {
                    const int nt = 2 * g + half;
                    #pragma unroll
                    for (int mt = 0; mt < 2; ++mt)
                        mma_f16(acc[mt][nt], af[mt], bf + 2 * half);
                }
            }
        }
        __syncthreads();
    }

    // epilogue: c0:(r,c) c1:(r,c+1) c2:(r+8,c) c3:(r+8,c+1)
    const int bb     = (int)(rowBase >> 14);
    const int mLocal = (int)(rowBase & 16383);
    #pragma unroll
    for (int mt = 0; mt < 2; ++mt)
        #pragma unroll
        for (int nt = 0; nt < 8; ++nt) {
            const int m0 = mLocal + wm * 32 + mt * 16 + (lane >> 2);
            const int n0 = wn * 64 + nt * 8 + 2 * (lane & 3);
            float* o0 = out + ((size_t)bb * DOUT_ + n0) * M_ + m0;
            o0[0]      = acc[mt][nt][0];
            o0[M_]     = acc[mt][nt][1];
            o0[8]      = acc[mt][nt][2];
            o0[M_ + 8] = acc[mt][nt][3];
        }
}

// ---------------------------------------------------------------------------
extern "C" void kernel_launch(void* const* d_in, const int* in_sizes, int n_in,
                              void* d_out, int out_size)
{
    // Dispatch inputs by (pairwise-distinct) element count:
    const float* points_xyz    = nullptr;
    const float* features      = nullptr;
    const float* center_xyz    = nullptr;
    const int*   neighbor_idx  = nullptr;
    const float* kernel_points = nullptr;
    const float* weights       = nullptr;

    for (int i = 0; i < n_in; i++) {
        switch (in_sizes[i]) {
            case 393216:  points_xyz    = (const float*)d_in[i]; break;
            case 8388608: features      = (const float*)d_in[i]; break;
            case 98304:   center_xyz    = (const float*)d_in[i]; break;
            case 1048576: neighbor_idx  = (const int*)d_in[i];   break;
            case 45:      kernel_points = (const float*)d_in[i]; break;
            case 122880:  weights       = (const float*)d_in[i]; break;
            default: break;
        }
    }
    float* out = (float*)d_out;

    cudaFuncSetAttribute(kpconv_mma_gemm,
                         cudaFuncAttributeMaxDynamicSharedMemorySize, GEMM_SMEM);
    cudaFuncSetAttribute(kpconv_weighted_mma,
                         cudaFuncAttributeMaxDynamicSharedMemorySize, K2_SMEM);
    cudaFuncSetAttribute(kpconv_weighted_mma,
                         cudaFuncAttributePreferredSharedMemoryCarveout, 100);

    dim3 g1(N_ / 32, DIN_ / 32, B_);
    transpose_feat_kernel<<<g1, dim3(32, 8)>>>(features);

    prep_w_kernel<<<(KP_ * DIN_ * DOUT_ + 255) / 256, 256>>>(weights);

    kpconv_weighted_mma<<<(B_ * M_) / PTS2, 256, K2_SMEM>>>(
        points_xyz, center_xyz, neighbor_idx, kernel_points);

    kpconv_mma_gemm<<<(B_ * M_) / 128, 256, GEMM_SMEM>>>(out);
}

// round 16
// speedup vs baseline: 1.7767x; 1.0732x over previous
#include <cuda_runtime.h>
#include <cuda_bf16.h>
#include <cuda_fp16.h>
#include <stdint.h>

#define B_     2
#define N_     65536
#define M_     16384
#define K_     32
#define KP_    15
#define DIN_   64
#define DOUT_  128
#define KTOT   960           // KP_*DIN_
#define SHADOW (-1000.0f)

// ---------------------------------------------------------------------------
// Scratch (__device__ globals per no-allocation rule)
// ---------------------------------------------------------------------------
__device__ __align__(16) __half g_featTh[(size_t)B_ * N_ * DIN_];  // 16.8 MB fp16
__device__ __align__(16) __half g_a[(size_t)B_ * M_ * KTOT];       // 60 MB (A fp16)
__device__ __align__(16) __half g_bh[DOUT_ * KTOT];                // W^T fp16

// ---------------------------------------------------------------------------
// helpers
// ---------------------------------------------------------------------------
__device__ __forceinline__ uint32_t smem_u32(const void* p) {
    uint32_t a;
    asm("{ .reg .u64 t; cvta.to.shared.u64 t, %1; cvt.u32.u64 %0, t; }"
        : "=r"(a) : "l"(p));
    return a;
}
__device__ __forceinline__ void ldsm4(uint32_t& r0, uint32_t& r1,
                                      uint32_t& r2, uint32_t& r3, uint32_t addr) {
    asm volatile("ldmatrix.sync.aligned.m8n8.x4.shared.b16 {%0,%1,%2,%3}, [%4];"
                 : "=r"(r0), "=r"(r1), "=r"(r2), "=r"(r3) : "r"(addr));
}
__device__ __forceinline__ void ldsm4t(uint32_t& r0, uint32_t& r1,
                                       uint32_t& r2, uint32_t& r3, uint32_t addr) {
    asm volatile("ldmatrix.sync.aligned.m8n8.x4.trans.shared.b16 {%0,%1,%2,%3}, [%4];"
                 : "=r"(r0), "=r"(r1), "=r"(r2), "=r"(r3) : "r"(addr));
}
__device__ __forceinline__ void mma_f16(float* c, const uint32_t* a,
                                        const uint32_t* b) {
    asm volatile("mma.sync.aligned.m16n8k16.row.col.f32.f16.f16.f32 "
                 "{%0,%1,%2,%3}, {%4,%5,%6,%7}, {%8,%9}, {%0,%1,%2,%3};"
                 : "+f"(c[0]), "+f"(c[1]), "+f"(c[2]), "+f"(c[3])
                 : "r"(a[0]), "r"(a[1]), "r"(a[2]), "r"(a[3]),
                   "r"(b[0]), "r"(b[1]));
}
__device__ __forceinline__ void cpasync16(uint32_t dst, const void* src) {
    asm volatile("cp.async.ca.shared.global [%0], [%1], 16;" :: "r"(dst), "l"(src));
}
__device__ __forceinline__ void cp_commit() {
    asm volatile("cp.async.commit_group;" ::: "memory");
}
__device__ __forceinline__ void cp_wait2() {
    asm volatile("cp.async.wait_group 2;" ::: "memory");
}
__device__ __forceinline__ void cp_wait1() {
    asm volatile("cp.async.wait_group 1;" ::: "memory");
}
__device__ __forceinline__ void cp_wait0() {
    asm volatile("cp.async.wait_group 0;" ::: "memory");
}
__device__ __forceinline__ uint32_t pkhf2(float a, float b) {
    __half2 t = __floats2half2_rn(a, b);
    return *(uint32_t*)&t;
}

// ---------------------------------------------------------------------------
// Kernel 1: transpose features [B][Din][N] -> g_featTh [B][N][Din] (fp16)
// ---------------------------------------------------------------------------
__global__ void transpose_feat_kernel(const float* __restrict__ f)
{
    __shared__ float tile[32][33];
    const int b  = blockIdx.z;
    const int n0 = blockIdx.x * 32;
    const int d0 = blockIdx.y * 32;
    const int x = threadIdx.x, y = threadIdx.y;

    #pragma unroll
    for (int i = y; i < 32; i += 8)
        tile[i][x] = f[((size_t)b * DIN_ + (d0 + i)) * N_ + n0 + x];
    __syncthreads();
    #pragma unroll
    for (int i = y; i < 32; i += 8)
        g_featTh[((size_t)b * N_ + (n0 + i)) * DIN_ + d0 + x] =
            __float2half_rn(tile[x][i]);
}

// ---------------------------------------------------------------------------
// Kernel 1b: weights [Kp][Din][Dout] -> g_bh [Dout rows][KTOT cols] (fp16)
// ---------------------------------------------------------------------------
__global__ void prep_w_kernel(const float* __restrict__ w)
{
    const int e = blockIdx.x * 256 + threadIdx.x;
    if (e >= KP_ * DIN_ * DOUT_) return;
    const int kp = e / DOUT_, o = e % DOUT_;
    g_bh[o * KTOT + kp] = __float2half_rn(w[e]);
}

// ---------------------------------------------------------------------------
// Kernel 2: einsum1 on tensor cores, single-fp16 w (error-budgeted).
//   warp <-> point; 8 points / 256-thr CTA; 16-row chunked F buffer.
// NOTE: neighbor_indices is int32 (JAX canonicalizes int64 -> int32).
// ---------------------------------------------------------------------------
#define PTS2   8
#define FSTR   72                        // feat smem row stride (fp16 elems)
#define WSTR   40                        // w smem row stride (fp16 elems)
#define F_BYTES (16 * FSTR * 2)          // 2304 (single fp16 chunk buffer)
#define W_BYTES (16 * WSTR * 2)          // 1280
#define PT_BYTES (F_BYTES + W_BYTES)     // 3584
#define K2_SMEM (PTS2 * PT_BYTES)        // 28672

__global__ __launch_bounds__(256)
void kpconv_weighted_mma(const float* __restrict__ points_xyz,
                         const float* __restrict__ center_xyz,
                         const int* __restrict__ nidx,
                         const float* __restrict__ kernel_points)
{
    extern __shared__ __align__(16) char k2sm[];
    const int wpt  = threadIdx.x >> 5;   // warp id == local point id
    const int lane = threadIdx.x & 31;
    const int bm   = blockIdx.x * PTS2 + wpt;
    const int b    = bm >> 14;

    __half* sF = (__half*)(k2sm + wpt * PT_BYTES);
    __half* sW = sF + 16 * FSTR;

    // ---- phase 1: lane = k; coords in registers
    const int ii0 = nidx[(size_t)bm * K_ + lane];
    const bool valid = (unsigned)ii0 < (unsigned)N_;
    const int idx = valid ? ii0 : 0;
    float px = SHADOW, py = SHADOW, pz = SHADOW;
    if (valid) {
        const float* pp = points_xyz + ((size_t)b * N_ + ii0) * 3;
        px = pp[0]; py = pp[1]; pz = pp[2];
    }
    const float rx = px - center_xyz[bm * 3 + 0];
    const float ry = py - center_xyz[bm * 3 + 1];
    const float rz = pz - center_xyz[bm * 3 + 2];
    float md = sqrtf(rx * rx + ry * ry + rz * rz);
    #pragma unroll
    for (int o = 16; o; o >>= 1)
        md = fmaxf(md, __shfl_xor_sync(0xffffffffu, md, o));
    const float inv = 1.0f / (md / 2.1f + 1e-5f);

    // ---- phase 2: w[p] -> A smem [p][k=lane], fp16; row 15 zero
    #pragma unroll
    for (int p = 0; p < KP_; ++p) {
        const float kx = kernel_points[p * 3 + 0] * md;
        const float ky = kernel_points[p * 3 + 1] * md;
        const float kz = kernel_points[p * 3 + 2] * md;
        const float dx = rx - kx, dy = ry - ky, dz = rz - kz;
        float w = 1.0f - sqrtf(dx * dx + dy * dy + dz * dz) * inv;
        w = valid ? fmaxf(w, 0.0f) : 0.0f;
        sW[p * WSTR + lane] = __float2half_rn(w);
    }
    sW[15 * WSTR + lane] = __float2half_rn(0.0f);

    float acc[8][4];
    #pragma unroll
    for (int j = 0; j < 8; ++j)
        #pragma unroll
        for (int q = 0; q < 4; ++q) acc[j][q] = 0.0f;

    const int ltile = lane >> 3, lr = lane & 7;
    const int aRow = (ltile & 1) * 8 + lr;
    const int aCol = (ltile >> 1) * 8;
    const int bRow = (ltile & 1) * 8 + lr;
    const int bCol = (ltile >> 1) * 8;
    const int grow = lane >> 3;           // row within 4-row gather group
    const int gseg = lane & 7;            // uint4 slot within 128B row
    const uint4* gfb = (const uint4*)(g_featTh + (size_t)b * N_ * DIN_);

    #pragma unroll
    for (int kc = 0; kc < 2; ++kc) {
        // ---- gather 16 fp16 feat rows: pure uint4 copy, 4 rows per pass
        #pragma unroll
        for (int pass = 0; pass < 4; ++pass) {
            const int kl = pass * 4 + grow;          // local row 0..15
            const int ik = __shfl_sync(0xffffffffu, idx, kc * 16 + kl);
            *(uint4*)&sF[kl * FSTR + gseg * 8] = gfb[(size_t)ik * 8 + gseg];
        }
        __syncwarp();

        // ---- A frag (w) + B frags (feat), 8 mma per chunk
        uint32_t ah[4];
        const uint32_t aOff = (uint32_t)(aRow * WSTR + kc * 16 + aCol) * 2;
        ldsm4(ah[0], ah[1], ah[2], ah[3], smem_u32(sW) + aOff);
        #pragma unroll
        for (int g = 0; g < 4; ++g) {                // n in 16-wide groups
            const uint32_t bOff = (uint32_t)(bRow * FSTR + g * 16 + bCol) * 2;
            uint32_t bf[4];
            ldsm4t(bf[0], bf[1], bf[2], bf[3], smem_u32(sF) + bOff);
            #pragma unroll
            for (int half = 0; half < 2; ++half)
                mma_f16(acc[2 * g + half], ah, bf + 2 * half);
        }
        __syncwarp();          // frags in regs; safe to overwrite buffer
    }

    // ---- epilogue: stage [p][64] fp16 into sF, then coalesced uint4 copy
    // (120 uint4) to gmem.
    __half* eF = sF;                      // 2048 B needed, 2304 available
    const int r  = lane >> 2;
    const int cb = 2 * (lane & 3);
    #pragma unroll
    for (int nt = 0; nt < 8; ++nt) {
        const int d0 = nt * 8 + cb;
        *(uint32_t*)&eF[r * 64 + d0]       = pkhf2(acc[nt][0], acc[nt][1]);
        // p = r+8 (8..15; row 15 staged but never copied out)
        *(uint32_t*)&eF[(r + 8) * 64 + d0] = pkhf2(acc[nt][2], acc[nt][3]);
    }
    __syncwarp();

    {
        const uint4* eh = (const uint4*)eF;
        uint4* wh = (uint4*)(g_a + (size_t)bm * KTOT);
        #pragma unroll
        for (int i = 0; i < 4; ++i) {
            const int e = lane + i * 32;      // 0..127, need 0..119
            if (e < 120) wh[e] = eh[e];
        }
    }
}

// ---------------------------------------------------------------------------
// Kernel 3: mma.sync fp16 GEMM, single-term, cp.async 4-stage pipeline.
//   Constant wait_group 2 in-loop, ONE __syncthreads per chunk, tail peeled.
//   Stage safety: at iter c a warp issues stage (c+2)&3; all warps have
//   passed sync c-1 so compute of c-2 (same stage) is complete; compute
//   stage c&3 and in-flight (c+1)&3/(c+2)&3 are disjoint.
// ---------------------------------------------------------------------------
#define BK    32
#define NCHUNK (KTOT / BK)       // 30
#define LDS_  40                 // row stride (elements): 80B, ldsm conflict-free
#define ARR_BYTES  (128 * LDS_ * 2)          // 10240 B per array
#define STAGE_BYTES (2 * ARR_BYTES)          // A, B = 20480 B
#define GEMM_SMEM  (4 * STAGE_BYTES)         // 81920 B

__global__ __launch_bounds__(256)
void kpconv_mma_gemm(float* __restrict__ out)
{
    extern __shared__ __align__(16) char sm[];
    const uint32_t smem_base = smem_u32(sm);

    const int tid  = threadIdx.x;
    const int wid  = tid >> 5, lane = tid & 31;
    const int wm   = wid & 3;        // warp m-offset: wm*32
    const int wn   = wid >> 2;       // warp n-offset: wn*64
    const size_t rowBase = (size_t)blockIdx.x * 128;

    auto issue_chunk = [&](int c, int stage) {
        const uint32_t sb = smem_base + stage * STAGE_BYTES;
        #pragma unroll
        for (int i = 0; i < 4; ++i) {
            const int idx = tid + i * 256;      // 0..1023
            const int arr = idx >> 9;           // 0..1
            const int rem = idx & 511;
            const int row = rem >> 2, seg = rem & 3;
            const uint32_t dst = sb + arr * ARR_BYTES + (row * LDS_ + seg * 8) * 2;
            const __half* src;
            if (arr == 0) src = g_a  + (rowBase + row) * KTOT + c * BK + seg * 8;
            else          src = g_bh + (size_t)row * KTOT + c * BK + seg * 8;
            cpasync16(dst, src);
        }
        cp_commit();
    };

    float acc[2][8][4];
    #pragma unroll
    for (int i = 0; i < 2; i++)
        #pragma unroll
        for (int j = 0; j < 8; j++)
            #pragma unroll
            for (int q = 0; q < 4; q++) acc[i][j][q] = 0.0f;

    // per-lane ldmatrix row/col patterns
    const int ltile = lane >> 3, lr = lane & 7;
    const int aRow = (ltile & 1) * 8 + lr;
    const int aCol = (ltile >> 1) * 8;
    const int bRow = (ltile >> 1) * 8 + lr;
    const int bCol = (ltile & 1) * 8;

    auto compute_chunk = [&](int stage) {
        const uint32_t sb = smem_base + stage * STAGE_BYTES;
        const uint32_t pA = sb;
        const uint32_t pB = sb + ARR_BYTES;
        #pragma unroll
        for (int kk = 0; kk < 2; ++kk) {
            const int kcol = kk * 16;
            uint32_t af[2][4];
            #pragma unroll
            for (int mt = 0; mt < 2; ++mt) {
                const int row = wm * 32 + mt * 16 + aRow;
                const int col = kcol + aCol;
                const uint32_t off = (uint32_t)(row * LDS_ + col) * 2;
                ldsm4(af[mt][0], af[mt][1], af[mt][2], af[mt][3], pA + off);
            }
            #pragma unroll
            for (int g = 0; g < 4; ++g) {
                const int row = wn * 64 + g * 16 + bRow;
                const int col = kcol + bCol;
                const uint32_t off = (uint32_t)(row * LDS_ + col) * 2;
                uint32_t bf[4];
                ldsm4(bf[0], bf[1], bf[2], bf[3], pB + off);
                #pragma unroll
                for (int half = 0; half < 2; ++half) {
                    const int nt = 2 * g + half;
                    #pragma unroll
                    for (int mt = 0; mt < 2; ++mt)
                        mma_f16(acc[mt][nt], af[mt], bf + 2 * half);
                }
            }
        }
    };

    issue_chunk(0, 0);
    issue_chunk(1, 1);

    for (int c = 0; c < NCHUNK - 2; ++c) {
        issue_chunk(c + 2, (c + 2) & 3);
        cp_wait2();
        __syncthreads();
        compute_chunk(c & 3);
    }
    // peeled tail (straight-line, no branchy wait ladder)
    cp_wait1();
    __syncthreads();
    compute_chunk((NCHUNK - 2) & 3);
    cp_wait0();
    __syncthreads();
    compute_chunk((NCHUNK - 1) & 3);

    // epilogue: c0:(r,c) c1:(r,c+1) c2:(r+8,c) c3:(r+8,c+1)
    const int bb     = (int)(rowBase >> 14);
    const int mLocal = (int)(rowBase & 16383);
    #pragma unroll
    for (int mt = 0; mt < 2; ++mt)
        #pragma unroll
        for (int nt = 0; nt < 8; ++nt) {
            const int m0 = mLocal + wm * 32 + mt * 16 + (lane >> 2);
            const int n0 = wn * 64 + nt * 8 + 2 * (lane & 3);
            float* o0 = out + ((size_t)bb * DOUT_ + n0) * M_ + m0;
            o0[0]      = acc[mt][nt][0];
            o0[M_]     = acc[mt][nt][1];
            o0[8]      = acc[mt][nt][2];
            o0[M_ + 8] = acc[mt][nt][3];
        }
}

// ---------------------------------------------------------------------------
extern "C" void kernel_launch(void* const* d_in, const int* in_sizes, int n_in,
                              void* d_out, int out_size)
{
    // Dispatch inputs by (pairwise-distinct) element count:
    const float* points_xyz    = nullptr;
    const float* features      = nullptr;
    const float* center_xyz    = nullptr;
    const int*   neighbor_idx  = nullptr;
    const float* kernel_points = nullptr;
    const float* weights       = nullptr;

    for (int i = 0; i < n_in; i++) {
        switch (in_sizes[i]) {
            case 393216:  points_xyz    = (const float*)d_in[i]; break;
            case 8388608: features      = (const float*)d_in[i]; break;
            case 98304:   center_xyz    = (const float*)d_in[i]; break;
            case 1048576: neighbor_idx  = (const int*)d_in[i];   break;
            case 45:      kernel_points = (const float*)d_in[i]; break;
            case 122880:  weights       = (const float*)d_in[i]; break;
            default: break;
        }
    }
    float* out = (float*)d_out;

    cudaFuncSetAttribute(kpconv_mma_gemm,
                         cudaFuncAttributeMaxDynamicSharedMemorySize, GEMM_SMEM);
    cudaFuncSetAttribute(kpconv_weighted_mma,
                         cudaFuncAttributeMaxDynamicSharedMemorySize, K2_SMEM);
    cudaFuncSetAttribute(kpconv_weighted_mma,
                         cudaFuncAttributePreferredSharedMemoryCarveout, 100);

    dim3 g1(N_ / 32, DIN_ / 32, B_);
    transpose_feat_kernel<<<g1, dim3(32, 8)>>>(features);

    prep_w_kernel<<<(KP_ * DIN_ * DOUT_ + 255) / 256, 256>>>(weights);

    kpconv_weighted_mma<<<(B_ * M_) / PTS2, 256, K2_SMEM>>>(
        points_xyz, center_xyz, neighbor_idx, kernel_points);

    kpconv_mma_gemm<<<(B_ * M_) / 128, 256, GEMM_SMEM>>>(out);
}